// round 13
// baseline (speedup 1.0000x reference)
#include <cuda_runtime.h>
#include <cuda_fp16.h>
#include <cstdint>

#define NN 100000
#define EE 1600000
#define DD 64
#define K1 10
#define K2 3
#define NB_SCAN ((NN + 1023) / 1024)

// ---------------- device scratch (allocation-free rule: __device__ globals) ----
__device__ int   g_deg[NN];
__device__ int   g_cursor[NN];
__device__ float g_dinv[NN];
__device__ int   g_off[NN + 1];
__device__ int   g_part[128];
__device__ __align__(16) int2   g_csc[EE];                          // (src, w-bits)
__device__ __align__(16) __half g_S1[(size_t)(K1 + 1) * NN * DD];   // 11 fp16 slices
__device__ __align__(16) __half g_S2[(size_t)(K2 + 1) * NN * DD];   // 4 fp16 slices
__device__ __align__(16) __half g_Sf[(size_t)NN * DD];              // layer2 out fp16
__device__ __align__(16) __half g_W1h[(K1 + 1) * DD * DD];
__device__ __align__(16) __half g_W2h[(K2 + 1) * DD * DD];
__device__ __align__(16) __half g_Wch[DD * DD];

// ---------------- build kernels ------------------------------------------------
__global__ void k_zero() {
    int i = blockIdx.x * blockDim.x + threadIdx.x;
    if (i < NN) { g_deg[i] = 0; g_cursor[i] = 0; }
}

__global__ void k_deg(const int* __restrict__ ei) {
    int e = blockIdx.x * blockDim.x + threadIdx.x;
    if (e < EE) atomicAdd(&g_deg[ei[EE + e]], 1);
}

// block-scan of deg -> g_off[i+1] (local), block sums -> g_part; also dinv
__global__ void k_scan1() {
    __shared__ int sd[1024];
    int b = blockIdx.x, t = threadIdx.x;
    int i = b * 1024 + t;
    int v = (i < NN) ? g_deg[i] : 0;
    if (i < NN) {
        float d = (float)v;
        g_dinv[i] = (d > 0.0f) ? rsqrtf(d) : 0.0f;
    }
    sd[t] = v;
    __syncthreads();
    for (int off = 1; off < 1024; off <<= 1) {
        int x = sd[t];
        if (t >= off) x += sd[t - off];
        __syncthreads();
        sd[t] = x;
        __syncthreads();
    }
    if (i < NN) g_off[i + 1] = sd[t];
    if (t == 1023) g_part[b] = sd[1023];
}

// each block recomputes the 98-partial prefix locally, adds to its g_off range
__global__ void k_scan3() {
    __shared__ int sp[128];
    int b = blockIdx.x, t = threadIdx.x;
    if (t < 128) sp[t] = (t < NB_SCAN) ? g_part[t] : 0;
    __syncthreads();
    for (int off = 1; off < 128; off <<= 1) {
        int x = 0;
        if (t < 128) { x = sp[t]; if (t >= off) x += sp[t - off]; }
        __syncthreads();
        if (t < 128) sp[t] = x;
        __syncthreads();
    }
    int add = (b > 0) ? sp[b - 1] : 0;
    int i = b * 1024 + t;
    if (i < NN) g_off[i + 1] += add;
    if (b == 0 && t == 0) g_off[0] = 0;
}

// fused: CSC fill (edges) + x -> fp16 slice0 copy. grid = NN*32/256 = 12500
__global__ void k_fillcopy(const int* __restrict__ ei, const float* __restrict__ x) {
    int i = blockIdx.x * blockDim.x + threadIdx.x;
    if (i < NN * 32) {
        float2 v = ((const float2*)x)[i];
        ((__half2*)g_S1)[i] = __floats2half2_rn(v.x, v.y);
    }
    if (i < EE) {
        int r = ei[i];
        int c = ei[EE + i];
        int p = g_off[c] + atomicAdd(&g_cursor[c], 1);
        g_csc[p] = make_int2(r, __float_as_int(g_dinv[r] * g_dinv[c]));
    }
}

// weights fp32 -> fp16 (one tiny launch)
__global__ void k_cvtw(const float* __restrict__ w1, const float* __restrict__ w2,
                       const float* __restrict__ wc) {
    int i = blockIdx.x * blockDim.x + threadIdx.x;
    if (i < (K1 + 1) * DD * DD) g_W1h[i] = __float2half_rn(w1[i]);
    if (i < (K2 + 1) * DD * DD) g_W2h[i] = __float2half_rn(w2[i]);
    if (i < DD * DD)            g_Wch[i] = __float2half_rn(wc[i]);
}

// ---------------- SpMM: TWO warps per dst node, 4 edges/warp-iteration ---------
// Pair of warps splits a node's edge list (stride 8); R11 inner loop per warp.
// lanes: eg = lane>>3 (edge group), c = lane&7 (16B chunk of the 128B row).
// Partials combined via 256B smem + one __syncthreads per block.
__global__ void __launch_bounds__(256) k_spmm(int layer, int si, int so) {
    __shared__ float red[4][8][8];            // [pair][chunk][8 floats]
    int wib = threadIdx.x >> 5;               // warp in block 0..7
    int pairL = wib >> 1;                     // 0..3
    int half = wib & 1;
    int node = blockIdx.x * 4 + pairL;
    int lane = threadIdx.x & 31;
    int eg = lane >> 3, c = lane & 7;

    const __half* base = layer ? g_S2 : g_S1;
    const __half* __restrict__ hin = base + (size_t)si * NN * DD;
    __half* __restrict__ hout = (layer ? g_S2 : g_S1) + (size_t)so * NN * DD;

    float acc[8];
#pragma unroll
    for (int j = 0; j < 8; j++) acc[j] = 0.f;

    if (node < NN) {
        int s = g_off[node], eend = g_off[node + 1];
#pragma unroll 2
        for (int p = s + half * 4 + eg; p < eend; p += 8) {
            int2 sw = __ldg(&g_csc[p]);
            float wt = __int_as_float(sw.y);
            uint4 v = __ldg((const uint4*)(hin + (size_t)sw.x * DD) + c);
            float2 f0 = __half22float2(*(__half2*)&v.x);
            float2 f1 = __half22float2(*(__half2*)&v.y);
            float2 f2 = __half22float2(*(__half2*)&v.z);
            float2 f3 = __half22float2(*(__half2*)&v.w);
            acc[0] += wt * f0.x; acc[1] += wt * f0.y;
            acc[2] += wt * f1.x; acc[3] += wt * f1.y;
            acc[4] += wt * f2.x; acc[5] += wt * f2.y;
            acc[6] += wt * f3.x; acc[7] += wt * f3.y;
        }
        // reduce across the 4 edge groups (lanes differing in bits 3,4)
#pragma unroll
        for (int j = 0; j < 8; j++) {
            acc[j] += __shfl_xor_sync(0xffffffffu, acc[j], 8);
            acc[j] += __shfl_xor_sync(0xffffffffu, acc[j], 16);
        }
        if (half == 1 && eg == 0) {
#pragma unroll
            for (int j = 0; j < 8; j++) red[pairL][c][j] = acc[j];
        }
    }
    __syncthreads();
    if (node < NN && half == 0 && eg == 0) {
#pragma unroll
        for (int j = 0; j < 8; j++) acc[j] += red[pairL][c][j];
        __half2 h0 = __floats2half2_rn(acc[0], acc[1]);
        __half2 h1 = __floats2half2_rn(acc[2], acc[3]);
        __half2 h2 = __floats2half2_rn(acc[4], acc[5]);
        __half2 h3 = __floats2half2_rn(acc[6], acc[7]);
        uint4 o;
        o.x = *(uint32_t*)&h0; o.y = *(uint32_t*)&h1;
        o.z = *(uint32_t*)&h2; o.w = *(uint32_t*)&h3;
        *((uint4*)(hout + (size_t)node * DD) + c) = o;
    }
}

// ---------------- tensor-core multi-slice GEMM ---------------------------------
// C[r][c] = (tanh?)( sum_s A_s[r][:] . W_s[:][c] + bias[c] ), fp16 in, fp32 acc.
__global__ void __launch_bounds__(256, 2) k_mma(
    int whichA, int nsl, int whichW,
    const float* __restrict__ bias,
    int whichOut, float* __restrict__ dext, int dotanh)
{
    __shared__ __half As[256 * 72];   // A tile, 72-half padded rows
    __shared__ __half Ws[64 * 72];    // W^T tile: [n][k], 72-half padded rows

    const __half* A = (whichA == 0) ? g_S1 : (whichA == 1) ? g_S2 : g_Sf;
    const __half* W = (whichW == 0) ? g_W1h : (whichW == 1) ? g_W2h : g_Wch;
    __half* OutH = (whichOut == 0) ? g_S2 : g_Sf;

    int t = threadIdx.x, w = t >> 5, l = t & 31;
    int rowBase = blockIdx.x * 256;

    float acc[2][8][4];
#pragma unroll
    for (int rf = 0; rf < 2; rf++)
#pragma unroll
        for (int j = 0; j < 8; j++)
#pragma unroll
            for (int q = 0; q < 4; q++) acc[rf][j][q] = 0.f;

    for (int s = 0; s < nsl; s++) {
        const __half* Ag = A + (size_t)s * NN * DD;
#pragma unroll
        for (int it = 0; it < 8; it++) {
            int idx = it * 256 + t;              // 0..2047
            int row = idx >> 3, c16 = idx & 7;
            int gr = rowBase + row;
            uint4 v = make_uint4(0, 0, 0, 0);
            if (gr < NN) v = *(const uint4*)(Ag + (size_t)gr * DD + c16 * 8);
            *(uint4*)(&As[row * 72 + c16 * 8]) = v;
        }
        const __half* Wg = W + s * DD * DD;
#pragma unroll
        for (int it = 0; it < 16; it++) {
            int idx = it * 256 + t;              // 0..4095
            int k = idx >> 6, n = idx & 63;
            Ws[n * 72 + k] = Wg[idx];
        }
        __syncthreads();

#pragma unroll
        for (int ks = 0; ks < 4; ks++) {
            uint32_t a[2][4];
#pragma unroll
            for (int rf = 0; rf < 2; rf++) {
                int row = w * 32 + rf * 16 + (l & 15);
                uint32_t addr = (uint32_t)__cvta_generic_to_shared(
                    &As[row * 72 + ks * 16 + (l >> 4) * 8]);
                asm volatile("ldmatrix.sync.aligned.m8n8.x4.shared.b16 {%0,%1,%2,%3},[%4];"
                             : "=r"(a[rf][0]), "=r"(a[rf][1]), "=r"(a[rf][2]), "=r"(a[rf][3])
                             : "r"(addr));
            }
#pragma unroll
            for (int j = 0; j < 8; j++) {
                int n = j * 8 + (l >> 2);
                int kk = ks * 16 + (l & 3) * 2;
                uint32_t b0 = *(const uint32_t*)(&Ws[n * 72 + kk]);
                uint32_t b1 = *(const uint32_t*)(&Ws[n * 72 + kk + 8]);
#pragma unroll
                for (int rf = 0; rf < 2; rf++) {
                    asm volatile(
                        "mma.sync.aligned.m16n8k16.row.col.f32.f16.f16.f32 "
                        "{%0,%1,%2,%3},{%4,%5,%6,%7},{%8,%9},{%0,%1,%2,%3};"
                        : "+f"(acc[rf][j][0]), "+f"(acc[rf][j][1]),
                          "+f"(acc[rf][j][2]), "+f"(acc[rf][j][3])
                        : "r"(a[rf][0]), "r"(a[rf][1]), "r"(a[rf][2]), "r"(a[rf][3]),
                          "r"(b0), "r"(b1));
                }
            }
        }
        __syncthreads();
    }

#pragma unroll
    for (int rf = 0; rf < 2; rf++) {
#pragma unroll
        for (int j = 0; j < 8; j++) {
            int r0 = rowBase + w * 32 + rf * 16 + (l >> 2);
            int c = j * 8 + (l & 3) * 2;
            float v0 = acc[rf][j][0] + bias[c];
            float v1 = acc[rf][j][1] + bias[c + 1];
            float v2 = acc[rf][j][2] + bias[c];
            float v3 = acc[rf][j][3] + bias[c + 1];
            if (dotanh) {
                v0 = tanhf(v0); v1 = tanhf(v1);
                v2 = tanhf(v2); v3 = tanhf(v3);
            }
            if (whichOut == 2) {
                if (r0 < NN)     *(float2*)&dext[(size_t)r0 * DD + c]       = make_float2(v0, v1);
                if (r0 + 8 < NN) *(float2*)&dext[(size_t)(r0 + 8) * DD + c] = make_float2(v2, v3);
            } else {
                if (r0 < NN)     *(__half2*)&OutH[(size_t)r0 * DD + c]       = __floats2half2_rn(v0, v1);
                if (r0 + 8 < NN) *(__half2*)&OutH[(size_t)(r0 + 8) * DD + c] = __floats2half2_rn(v2, v3);
            }
        }
    }
}

// ---------------- launch -------------------------------------------------------
extern "C" void kernel_launch(void* const* d_in, const int* in_sizes, int n_in,
                              void* d_out, int out_size) {
    const float* x  = (const float*)d_in[0];
    const int*   ei = (const int*)d_in[1];     // int32 edge_index [2, E]
    const float* w1 = (const float*)d_in[2];
    const float* b1 = (const float*)d_in[3];
    const float* w2 = (const float*)d_in[4];
    const float* b2 = (const float*)d_in[5];
    const float* wc = (const float*)d_in[6];
    const float* bc = (const float*)d_in[7];
    float* out = (float*)d_out;

    // ---- build ----
    k_zero<<<(NN + 255) / 256, 256>>>();
    k_deg<<<(EE + 255) / 256, 256>>>(ei);
    k_scan1<<<NB_SCAN, 1024>>>();
    k_scan3<<<NB_SCAN, 1024>>>();
    k_fillcopy<<<(NN * 32 + 255) / 256, 256>>>(ei, x);

    int spmm_blocks = (NN + 3) / 4;     // 4 nodes (8 warps) per 256-thread block
    for (int k = 1; k <= K1; k++)
        k_spmm<<<spmm_blocks, 256>>>(0, k - 1, k);

    k_cvtw<<<((K1 + 1) * DD * DD + 255) / 256, 256>>>(w1, w2, wc);

    int gemm_blocks = (NN + 255) / 256;
    // layer1: tanh(sum H1_k W1_k + b1) -> g_S2 slice 0 (fp16)
    k_mma<<<gemm_blocks, 256>>>(0, K1 + 1, 0, b1, 0, nullptr, 1);

    for (int k = 1; k <= K2; k++)
        k_spmm<<<spmm_blocks, 256>>>(1, k - 1, k);
    // layer2: tanh(sum H2_k W2_k + b2) -> g_Sf (fp16)
    k_mma<<<gemm_blocks, 256>>>(1, K2 + 1, 1, b2, 1, nullptr, 1);

    // final linear -> d_out (fp32)
    k_mma<<<gemm_blocks, 256>>>(2, 1, 2, bc, 2, out, 0);
}

// round 14
// speedup vs baseline: 1.4629x; 1.4629x over previous
#include <cuda_runtime.h>
#include <cuda_fp16.h>
#include <cstdint>

#define NN 100000
#define EE 1600000
#define DD 64
#define K1 10
#define K2 3
#define NB_SCAN ((NN + 1023) / 1024)

// ---------------- device scratch (allocation-free rule: __device__ globals) ----
__device__ int   g_deg[NN];
__device__ int   g_cursor[NN];
__device__ float g_dinv[NN];
__device__ int   g_off[NN + 1];
__device__ int   g_part[128];
__device__ __align__(16) int2   g_csc[EE];                          // (src, w-bits)
__device__ __align__(16) __half g_S1[(size_t)(K1 + 1) * NN * DD];   // 11 fp16 slices
__device__ __align__(16) __half g_S2[(size_t)(K2 + 1) * NN * DD];   // 4 fp16 slices
__device__ __align__(16) __half g_Sf[(size_t)NN * DD];              // layer2 out fp16
// W transposed to [s][n][k] fp16 for direct cp.async tiling
__device__ __align__(16) __half g_W1T[(K1 + 1) * DD * DD];
__device__ __align__(16) __half g_W2T[(K2 + 1) * DD * DD];
__device__ __align__(16) __half g_WcT[DD * DD];

// ---------------- build kernels ------------------------------------------------
__global__ void k_zero() {
    int i = blockIdx.x * blockDim.x + threadIdx.x;
    if (i < NN) { g_deg[i] = 0; g_cursor[i] = 0; }
}

__global__ void k_deg(const int* __restrict__ ei) {
    int e = blockIdx.x * blockDim.x + threadIdx.x;
    if (e < EE) atomicAdd(&g_deg[ei[EE + e]], 1);
}

// block-scan of deg -> g_off[i+1] (local), block sums -> g_part; also dinv
__global__ void k_scan1() {
    __shared__ int sd[1024];
    int b = blockIdx.x, t = threadIdx.x;
    int i = b * 1024 + t;
    int v = (i < NN) ? g_deg[i] : 0;
    if (i < NN) {
        float d = (float)v;
        g_dinv[i] = (d > 0.0f) ? rsqrtf(d) : 0.0f;
    }
    sd[t] = v;
    __syncthreads();
    for (int off = 1; off < 1024; off <<= 1) {
        int x = sd[t];
        if (t >= off) x += sd[t - off];
        __syncthreads();
        sd[t] = x;
        __syncthreads();
    }
    if (i < NN) g_off[i + 1] = sd[t];
    if (t == 1023) g_part[b] = sd[1023];
}

// each block recomputes the 98-partial prefix locally, adds to its g_off range
__global__ void k_scan3() {
    __shared__ int sp[128];
    int b = blockIdx.x, t = threadIdx.x;
    if (t < 128) sp[t] = (t < NB_SCAN) ? g_part[t] : 0;
    __syncthreads();
    for (int off = 1; off < 128; off <<= 1) {
        int x = 0;
        if (t < 128) { x = sp[t]; if (t >= off) x += sp[t - off]; }
        __syncthreads();
        if (t < 128) sp[t] = x;
        __syncthreads();
    }
    int add = (b > 0) ? sp[b - 1] : 0;
    int i = b * 1024 + t;
    if (i < NN) g_off[i + 1] += add;
    if (b == 0 && t == 0) g_off[0] = 0;
}

// fused: CSC fill (edges) + x -> fp16 slice0 copy. grid = NN*32/256 = 12500
__global__ void k_fillcopy(const int* __restrict__ ei, const float* __restrict__ x) {
    int i = blockIdx.x * blockDim.x + threadIdx.x;
    if (i < NN * 32) {
        float2 v = ((const float2*)x)[i];
        ((__half2*)g_S1)[i] = __floats2half2_rn(v.x, v.y);
    }
    if (i < EE) {
        int r = ei[i];
        int c = ei[EE + i];
        int p = g_off[c] + atomicAdd(&g_cursor[c], 1);
        g_csc[p] = make_int2(r, __float_as_int(g_dinv[r] * g_dinv[c]));
    }
}

// weights fp32 [s][k][n] -> fp16 transposed [s][n][k]
__global__ void k_cvtw(const float* __restrict__ w1, const float* __restrict__ w2,
                       const float* __restrict__ wc) {
    int i = blockIdx.x * blockDim.x + threadIdx.x;
    int s = i >> 12, r = i & 4095;
    int k = r >> 6, n = r & 63;
    int to = (s << 12) + (n << 6) + k;
    if (i < (K1 + 1) * DD * DD) g_W1T[to] = __float2half_rn(w1[i]);
    if (i < (K2 + 1) * DD * DD) g_W2T[to] = __float2half_rn(w2[i]);
    if (i < DD * DD)            g_WcT[to] = __float2half_rn(wc[i]);
}

// ---------------- SpMM: warp per dst node, 4 edges/iteration (R11 form) --------
__global__ void __launch_bounds__(256) k_spmm(int layer, int si, int so) {
    int warp = (blockIdx.x * blockDim.x + threadIdx.x) >> 5;
    int lane = threadIdx.x & 31;
    if (warp >= NN) return;
    const __half* base = layer ? g_S2 : g_S1;
    const __half* __restrict__ hin = base + (size_t)si * NN * DD;
    __half* __restrict__ hout = (layer ? g_S2 : g_S1) + (size_t)so * NN * DD;
    int s = g_off[warp], eend = g_off[warp + 1];
    int eg = lane >> 3, c = lane & 7;

    float acc[8];
#pragma unroll
    for (int j = 0; j < 8; j++) acc[j] = 0.f;

#pragma unroll 2
    for (int p = s + eg; p < eend; p += 4) {
        int2 sw = __ldg(&g_csc[p]);
        float wt = __int_as_float(sw.y);
        uint4 v = __ldg((const uint4*)(hin + (size_t)sw.x * DD) + c);
        float2 f0 = __half22float2(*(__half2*)&v.x);
        float2 f1 = __half22float2(*(__half2*)&v.y);
        float2 f2 = __half22float2(*(__half2*)&v.z);
        float2 f3 = __half22float2(*(__half2*)&v.w);
        acc[0] += wt * f0.x; acc[1] += wt * f0.y;
        acc[2] += wt * f1.x; acc[3] += wt * f1.y;
        acc[4] += wt * f2.x; acc[5] += wt * f2.y;
        acc[6] += wt * f3.x; acc[7] += wt * f3.y;
    }

#pragma unroll
    for (int j = 0; j < 8; j++) {
        acc[j] += __shfl_xor_sync(0xffffffffu, acc[j], 8);
        acc[j] += __shfl_xor_sync(0xffffffffu, acc[j], 16);
    }

    if (eg == 0) {
        __half2 h0 = __floats2half2_rn(acc[0], acc[1]);
        __half2 h1 = __floats2half2_rn(acc[2], acc[3]);
        __half2 h2 = __floats2half2_rn(acc[4], acc[5]);
        __half2 h3 = __floats2half2_rn(acc[6], acc[7]);
        uint4 o;
        o.x = *(uint32_t*)&h0; o.y = *(uint32_t*)&h1;
        o.z = *(uint32_t*)&h2; o.w = *(uint32_t*)&h3;
        *((uint4*)(hout + (size_t)warp * DD) + c) = o;
    }
}

// ---------------- cp.async helpers ---------------------------------------------
__device__ __forceinline__ void cp16(uint32_t daddr, const void* src) {
    asm volatile("cp.async.ca.shared.global [%0], [%1], 16;\n" :: "r"(daddr), "l"(src));
}
__device__ __forceinline__ void cp_commit() {
    asm volatile("cp.async.commit_group;\n");
}
template <int N>
__device__ __forceinline__ void cp_wait() {
    asm volatile("cp.async.wait_group %0;\n" :: "n"(N));
}

// ---------------- tensor-core multi-slice GEMM, cp.async double-buffered -------
// C[r][c] = (tanh?)( sum_s A_s[r][:] . WT_s[c][:] + bias[c] ), fp16 in, fp32 acc.
// Dynamic smem: As[2] 256x72 halves + Ws[2] 64x72 halves = 92160 B, 2 blocks/SM.
#define AS_H (256 * 72)
#define WS_H (64 * 72)
__global__ void __launch_bounds__(256, 2) k_mma(
    int whichA, int nsl, int whichW,
    const float* __restrict__ bias,
    int whichOut, float* __restrict__ dext, int dotanh)
{
    extern __shared__ __half sh[];
    __half* AsB[2] = { sh, sh + AS_H };
    __half* WsB[2] = { sh + 2 * AS_H, sh + 2 * AS_H + WS_H };

    const __half* A = (whichA == 0) ? g_S1 : (whichA == 1) ? g_S2 : g_Sf;
    const __half* W = (whichW == 0) ? g_W1T : (whichW == 1) ? g_W2T : g_WcT;
    __half* OutH = (whichOut == 0) ? g_S2 : g_Sf;

    int t = threadIdx.x, w = t >> 5, l = t & 31;
    int rowBase = blockIdx.x * 256;

    // async load of slice s into buffer b
    auto load_slice = [&](int s, int b) {
        const __half* Ag = A + (size_t)s * NN * DD;
        __half* As = AsB[b];
#pragma unroll
        for (int it = 0; it < 8; it++) {
            int idx = it * 256 + t;              // 0..2047
            int row = idx >> 3, c16 = idx & 7;
            int gr = rowBase + row;
            __half* dst = As + row * 72 + c16 * 8;
            uint32_t da = (uint32_t)__cvta_generic_to_shared(dst);
            if (gr < NN) {
                cp16(da, Ag + (size_t)gr * DD + c16 * 8);
            } else {
                *(uint4*)dst = make_uint4(0, 0, 0, 0);
            }
        }
        const __half* Wg = W + s * DD * DD;      // [n][k]
        __half* Ws = WsB[b];
#pragma unroll
        for (int it = 0; it < 2; it++) {
            int idx = it * 256 + t;              // 0..511
            int n = idx >> 3, k8 = idx & 7;
            uint32_t da = (uint32_t)__cvta_generic_to_shared(Ws + n * 72 + k8 * 8);
            cp16(da, Wg + n * DD + k8 * 8);
        }
        cp_commit();
    };

    float acc[2][8][4];
#pragma unroll
    for (int rf = 0; rf < 2; rf++)
#pragma unroll
        for (int j = 0; j < 8; j++)
#pragma unroll
            for (int q = 0; q < 4; q++) acc[rf][j][q] = 0.f;

    load_slice(0, 0);

    for (int s = 0; s < nsl; s++) {
        int b = s & 1;
        if (s + 1 < nsl) { load_slice(s + 1, b ^ 1); cp_wait<1>(); }
        else             { cp_wait<0>(); }
        __syncthreads();

        const __half* As = AsB[b];
        const __half* Ws = WsB[b];
#pragma unroll
        for (int ks = 0; ks < 4; ks++) {
            uint32_t a[2][4];
#pragma unroll
            for (int rf = 0; rf < 2; rf++) {
                int row = w * 32 + rf * 16 + (l & 15);
                uint32_t addr = (uint32_t)__cvta_generic_to_shared(
                    &As[row * 72 + ks * 16 + (l >> 4) * 8]);
                asm volatile("ldmatrix.sync.aligned.m8n8.x4.shared.b16 {%0,%1,%2,%3},[%4];"
                             : "=r"(a[rf][0]), "=r"(a[rf][1]), "=r"(a[rf][2]), "=r"(a[rf][3])
                             : "r"(addr));
            }
#pragma unroll
            for (int j = 0; j < 8; j++) {
                int n = j * 8 + (l >> 2);
                int kk = ks * 16 + (l & 3) * 2;
                uint32_t b0 = *(const uint32_t*)(&Ws[n * 72 + kk]);
                uint32_t b1 = *(const uint32_t*)(&Ws[n * 72 + kk + 8]);
#pragma unroll
                for (int rf = 0; rf < 2; rf++) {
                    asm volatile(
                        "mma.sync.aligned.m16n8k16.row.col.f32.f16.f16.f32 "
                        "{%0,%1,%2,%3},{%4,%5,%6,%7},{%8,%9},{%0,%1,%2,%3};"
                        : "+f"(acc[rf][j][0]), "+f"(acc[rf][j][1]),
                          "+f"(acc[rf][j][2]), "+f"(acc[rf][j][3])
                        : "r"(a[rf][0]), "r"(a[rf][1]), "r"(a[rf][2]), "r"(a[rf][3]),
                          "r"(b0), "r"(b1));
                }
            }
        }
        __syncthreads();   // all warps done with buf b before it is refilled
    }

#pragma unroll
    for (int rf = 0; rf < 2; rf++) {
#pragma unroll
        for (int j = 0; j < 8; j++) {
            int r0 = rowBase + w * 32 + rf * 16 + (l >> 2);
            int c = j * 8 + (l & 3) * 2;
            float v0 = acc[rf][j][0] + bias[c];
            float v1 = acc[rf][j][1] + bias[c + 1];
            float v2 = acc[rf][j][2] + bias[c];
            float v3 = acc[rf][j][3] + bias[c + 1];
            if (dotanh) {
                v0 = tanhf(v0); v1 = tanhf(v1);
                v2 = tanhf(v2); v3 = tanhf(v3);
            }
            if (whichOut == 2) {
                if (r0 < NN)     *(float2*)&dext[(size_t)r0 * DD + c]       = make_float2(v0, v1);
                if (r0 + 8 < NN) *(float2*)&dext[(size_t)(r0 + 8) * DD + c] = make_float2(v2, v3);
            } else {
                if (r0 < NN)     *(__half2*)&OutH[(size_t)r0 * DD + c]       = __floats2half2_rn(v0, v1);
                if (r0 + 8 < NN) *(__half2*)&OutH[(size_t)(r0 + 8) * DD + c] = __floats2half2_rn(v2, v3);
            }
        }
    }
}

// ---------------- launch -------------------------------------------------------
extern "C" void kernel_launch(void* const* d_in, const int* in_sizes, int n_in,
                              void* d_out, int out_size) {
    const float* x  = (const float*)d_in[0];
    const int*   ei = (const int*)d_in[1];     // int32 edge_index [2, E]
    const float* w1 = (const float*)d_in[2];
    const float* b1 = (const float*)d_in[3];
    const float* w2 = (const float*)d_in[4];
    const float* b2 = (const float*)d_in[5];
    const float* wc = (const float*)d_in[6];
    const float* bc = (const float*)d_in[7];
    float* out = (float*)d_out;

    const int SMEM = (2 * AS_H + 2 * WS_H) * 2;   // 92160 B
    cudaFuncSetAttribute(k_mma, cudaFuncAttributeMaxDynamicSharedMemorySize, SMEM);

    // ---- build ----
    k_zero<<<(NN + 255) / 256, 256>>>();
    k_deg<<<(EE + 255) / 256, 256>>>(ei);
    k_scan1<<<NB_SCAN, 1024>>>();
    k_scan3<<<NB_SCAN, 1024>>>();
    k_cvtw<<<((K1 + 1) * DD * DD + 255) / 256, 256>>>(w1, w2, wc);
    k_fillcopy<<<(NN * 32 + 255) / 256, 256>>>(ei, x);

    int spmm_blocks = (NN * 32 + 255) / 256;
    for (int k = 1; k <= K1; k++)
        k_spmm<<<spmm_blocks, 256>>>(0, k - 1, k);

    int gemm_blocks = (NN + 255) / 256;
    // layer1: tanh(sum H1_k W1_k + b1) -> g_S2 slice 0 (fp16)
    k_mma<<<gemm_blocks, 256, SMEM>>>(0, K1 + 1, 0, b1, 0, nullptr, 1);

    for (int k = 1; k <= K2; k++)
        k_spmm<<<spmm_blocks, 256>>>(1, k - 1, k);
    // layer2: tanh(sum H2_k W2_k + b2) -> g_Sf (fp16)
    k_mma<<<gemm_blocks, 256, SMEM>>>(1, K2 + 1, 1, b2, 1, nullptr, 1);

    // final linear -> d_out (fp32)
    k_mma<<<gemm_blocks, 256, SMEM>>>(2, 1, 2, bc, 2, out, 0);
}